// round 4
// baseline (speedup 1.0000x reference)
#include <cuda_runtime.h>
#include <math.h>

// Problem constants (B=4, S=2048, D_IN=1024, D_OUT=1024, E=8, K=2)
#define BTOK    8192
#define DIN     1024
#define DOUT    1024
#define NE      8
#define NROW    24         // 8 gate rows + 16 expert rows (e, o in {0,1})
#define SPLITK  8
#define KSPAN   (DIN / SPLITK)   // 128
#define TMB     64         // tokens per GEMM block (2 warps)
#define GTHREADS 64

#define XS_STRIDE 132      // float4-aligned padded row
#define WS_STRIDE 132

// Transposed partials: scratch[(split*NROW + row)*BTOK + token]
__device__ float g_scratch[SPLITK * NROW * BTOK];   // 6.29 MB

__device__ __forceinline__ unsigned long long fma2(unsigned long long a,
                                                   unsigned long long b,
                                                   unsigned long long c) {
    unsigned long long d;
    asm("fma.rn.f32x2 %0, %1, %2, %3;" : "=l"(d) : "l"(a), "l"(b), "l"(c));
    return d;
}
__device__ __forceinline__ void unpack2(unsigned long long v, float& lo, float& hi) {
    asm("mov.b64 {%0, %1}, %2;" : "=f"(lo), "=f"(hi) : "l"(v));
}

// ---------------------------------------------------------------------------
// Kernel 1: split-K skinny GEMM, warp-per-32-tokens, broadcast weights, FFMA2
// ---------------------------------------------------------------------------
__global__ __launch_bounds__(GTHREADS)
void moe_gemm_kernel(const float* __restrict__ x,
                     const float* __restrict__ gate_w,
                     const float* __restrict__ expert_w)
{
    __shared__ float xs[TMB][XS_STRIDE];     // 33792 B
    __shared__ float ws[NROW][WS_STRIDE];    // 12672 B

    const int tid   = threadIdx.x;
    const int split = blockIdx.x & (SPLITK - 1);
    const int tb    = blockIdx.x >> 3;
    const int tok0  = tb * TMB;
    const int kbase = split * KSPAN;
    const int wid   = tid >> 5;
    const int lane  = tid & 31;

    // ---- load x tile: 64 tokens x 128 floats = 2048 float4 ----
    #pragma unroll
    for (int j = 0; j < (TMB * KSPAN) / (4 * GTHREADS); j++) {   // 32
        int i  = tid + j * GTHREADS;
        int m  = i >> 5;
        int f4 = (i & 31) << 2;
        float4 v = *(const float4*)(x + (size_t)(tok0 + m) * DIN + kbase + f4);
        *(float4*)&xs[m][f4] = v;
    }

    // ---- load weight tile: 24 rows x 128 floats = 768 float4 ----
    #pragma unroll
    for (int j = 0; j < (NROW * KSPAN) / (4 * GTHREADS); j++) {  // 12
        int i   = tid + j * GTHREADS;
        int row = i >> 5;
        int f4  = (i & 31) << 2;
        const float* src = (row < NE)
            ? (gate_w + (size_t)row * DIN)
            : (expert_w + ((size_t)(((row - NE) >> 1) * DOUT + ((row - NE) & 1))) * DIN);
        float4 v = *(const float4*)(src + kbase + f4);
        *(float4*)&ws[row][f4] = v;
    }

    __syncthreads();

    // ---- compute: lane = token, all 24 rows, packed f32x2 over k-pairs ----
    const float* xr = &xs[(wid << 5) + lane][0];

    unsigned long long acc[NROW];
    #pragma unroll
    for (int r = 0; r < NROW; r++) acc[r] = 0ULL;

    #pragma unroll 4
    for (int kk = 0; kk < KSPAN; kk += 4) {
        ulonglong2 xv = *(const ulonglong2*)(xr + kk);     // (x[k],x[k+1]),(x[k+2],x[k+3])
        #pragma unroll
        for (int r = 0; r < NROW; r++) {
            ulonglong2 wv = *(const ulonglong2*)(&ws[r][kk]);   // warp-broadcast
            acc[r] = fma2(xv.x, wv.x, acc[r]);
            acc[r] = fma2(xv.y, wv.y, acc[r]);
        }
    }

    // ---- write partials, transposed & coalesced: [split][row][token] ----
    const int token = tok0 + (wid << 5) + lane;
    #pragma unroll
    for (int r = 0; r < NROW; r++) {
        float lo, hi;
        unpack2(acc[r], lo, hi);
        g_scratch[((size_t)(split * NROW + r)) * BTOK + token] = lo + hi;
    }
}

// ---------------------------------------------------------------------------
// Kernel 2: reduce partials + gating epilogue + broadcast write
// ---------------------------------------------------------------------------
#define ETOK 16
#define ETHREADS 128

__global__ __launch_bounds__(ETHREADS)
void moe_epilogue_kernel(const float* __restrict__ gate_b,
                         const float* __restrict__ ebias,
                         const float* __restrict__ expert_b,
                         float* __restrict__ out,
                         float* __restrict__ idx_out)
{
    __shared__ float wtok[ETOK];
    const int tid  = threadIdx.x;
    const int tok0 = blockIdx.x * ETOK;

    if (tid < ETOK) {
        const int token = tok0 + tid;

        float P[NROW];
        #pragma unroll
        for (int r = 0; r < NROW; r++) P[r] = 0.f;
        #pragma unroll
        for (int s = 0; s < SPLITK; s++)
            #pragma unroll
            for (int r = 0; r < NROW; r++)
                P[r] += g_scratch[((size_t)(s * NROW + r)) * BTOK + token];

        float l[NE];
        #pragma unroll
        for (int e = 0; e < NE; e++)
            l[e] = P[e] + gate_b[e] + ebias[e];

        int e0 = 0; float b0 = l[0];
        #pragma unroll
        for (int e = 1; e < NE; e++)
            if (l[e] > b0) { b0 = l[e]; e0 = e; }
        int e1 = -1; float b1 = -INFINITY;
        #pragma unroll
        for (int e = 0; e < NE; e++) {
            if (e == e0) continue;
            if (l[e] > b1) { b1 = l[e]; e1 = e; }
        }

        float p0 = 1.f / (1.f + expf(-b0));
        float p1 = 1.f / (1.f + expf(-b1));
        float inv = 1.f / (p0 + p1);

        float v0 = P[NE + e0 * 2 + 0] + expert_b[(size_t)e0 * DOUT + 0];
        float v1 = P[NE + e1 * 2 + 1] + expert_b[(size_t)e1 * DOUT + 1];
        wtok[tid] = (v0 * p0 + v1 * p1) * inv;

        if (idx_out) {
            idx_out[(size_t)token * 2 + 0] = (float)e0;
            idx_out[(size_t)token * 2 + 1] = (float)e1;
        }
    }
    __syncthreads();

    // broadcast write: per token 1024 floats; 128 threads x 2 float4
    const int fo = tid << 2;                 // 0..508
    #pragma unroll 4
    for (int m = 0; m < ETOK; m++) {
        float v = wtok[m];
        float4 v4 = make_float4(v, v, v, v);
        float* base = out + (size_t)(tok0 + m) * DOUT;
        *(float4*)(base + fo) = v4;
        *(float4*)(base + 512 + fo) = v4;
    }
}

extern "C" void kernel_launch(void* const* d_in, const int* in_sizes, int n_in,
                              void* d_out, int out_size)
{
    const float* x        = (const float*)d_in[0];
    const float* gate_w   = (const float*)d_in[1];
    const float* gate_b   = (const float*)d_in[2];
    const float* ebias    = (const float*)d_in[3];
    const float* expert_w = (const float*)d_in[4];
    const float* expert_b = (const float*)d_in[5];
    float* out = (float*)d_out;

    float* idx_out = nullptr;
    long long base = (long long)BTOK * DOUT;
    if ((long long)out_size >= base + (long long)BTOK * 2)
        idx_out = out + base;

    moe_gemm_kernel<<<(BTOK / TMB) * SPLITK, GTHREADS>>>(x, gate_w, expert_w);
    moe_epilogue_kernel<<<BTOK / ETOK, ETHREADS>>>(gate_b, ebias, expert_b,
                                                   out, idx_out);
}

// round 5
// speedup vs baseline: 1.1974x; 1.1974x over previous
#include <cuda_runtime.h>
#include <math.h>

// Problem constants (B=4, S=2048, D_IN=1024, D_OUT=1024, E=8, K=2)
#define BTOK    8192
#define DIN     1024
#define DOUT    1024
#define NE      8
#define NROW    24         // 8 gate rows + 16 expert rows (e, o in {0,1})
#define SPLITK  4
#define KSPAN   (DIN / SPLITK)   // 256
#define TK      128        // k sub-chunk
#define TMB     64         // tokens per GEMM block (2 warps, lane = token)
#define GTHREADS 64

#define XS_STRIDE 132      // float4-aligned padded row
#define WS_STRIDE 132

// Transposed partials: scratch[(split*NROW + row)*BTOK + token]
__device__ float g_scratch[SPLITK * NROW * BTOK];   // 3.1 MB

__device__ __forceinline__ unsigned long long fma2(unsigned long long a,
                                                   unsigned long long b,
                                                   unsigned long long c) {
    unsigned long long d;
    asm("fma.rn.f32x2 %0, %1, %2, %3;" : "=l"(d) : "l"(a), "l"(b), "l"(c));
    return d;
}
__device__ __forceinline__ void unpack2(unsigned long long v, float& lo, float& hi) {
    asm("mov.b64 {%0, %1}, %2;" : "=f"(lo), "=f"(hi) : "l"(v));
}

// ---------------------------------------------------------------------------
// Kernel 1: split-K skinny GEMM, lane = token, broadcast weights, FFMA2
// ---------------------------------------------------------------------------
__global__ __launch_bounds__(GTHREADS)
void moe_gemm_kernel(const float* __restrict__ x,
                     const float* __restrict__ gate_w,
                     const float* __restrict__ expert_w)
{
    __shared__ float xs[TMB][XS_STRIDE];     // 33792 B
    __shared__ float ws[NROW][WS_STRIDE];    // 12672 B

    const int tid   = threadIdx.x;
    const int split = blockIdx.x & (SPLITK - 1);
    const int tb    = blockIdx.x >> 2;
    const int tok0  = tb * TMB;
    const int kbase = split * KSPAN;
    const int wid   = tid >> 5;
    const int lane  = tid & 31;

    unsigned long long acc[NROW];
    #pragma unroll
    for (int r = 0; r < NROW; r++) acc[r] = 0ULL;

    #pragma unroll
    for (int c = 0; c < KSPAN / TK; c++) {               // 2 chunks
        const int k0 = kbase + c * TK;
        __syncthreads();

        // ---- x chunk: 64 tokens x 128 floats = 2048 float4 ----
        #pragma unroll
        for (int j = 0; j < (TMB * TK) / (4 * GTHREADS); j++) {   // 32
            int i  = tid + j * GTHREADS;
            int m  = i >> 5;
            int f4 = (i & 31) << 2;
            float4 v = *(const float4*)(x + (size_t)(tok0 + m) * DIN + k0 + f4);
            *(float4*)&xs[m][f4] = v;
        }

        // ---- weight chunk: 24 rows x 128 floats = 768 float4 ----
        #pragma unroll
        for (int j = 0; j < (NROW * TK) / (4 * GTHREADS); j++) {  // 12
            int i   = tid + j * GTHREADS;
            int row = i >> 5;
            int f4  = (i & 31) << 2;
            const float* src = (row < NE)
                ? (gate_w + (size_t)row * DIN)
                : (expert_w + ((size_t)(((row - NE) >> 1) * DOUT + ((row - NE) & 1))) * DIN);
            float4 v = *(const float4*)(src + k0 + f4);
            *(float4*)&ws[row][f4] = v;
        }

        __syncthreads();

        // ---- compute: lane = token, all 24 rows, FFMA2 over k-pairs ----
        const float* xr = &xs[(wid << 5) + lane][0];
        #pragma unroll 4
        for (int kk = 0; kk < TK; kk += 4) {
            ulonglong2 xv = *(const ulonglong2*)(xr + kk);
            #pragma unroll
            for (int r = 0; r < NROW; r++) {
                ulonglong2 wv = *(const ulonglong2*)(&ws[r][kk]);  // warp-broadcast
                acc[r] = fma2(xv.x, wv.x, acc[r]);
                acc[r] = fma2(xv.y, wv.y, acc[r]);
            }
        }
    }

    // ---- write partials, transposed & coalesced: [split][row][token] ----
    const int token = tok0 + (wid << 5) + lane;
    #pragma unroll
    for (int r = 0; r < NROW; r++) {
        float lo, hi;
        unpack2(acc[r], lo, hi);
        g_scratch[((size_t)(split * NROW + r)) * BTOK + token] = lo + hi;
    }
}

// ---------------------------------------------------------------------------
// Kernel 2: parallel reduce + gating epilogue + broadcast write
// ---------------------------------------------------------------------------
#define ETOK 32
#define ETHREADS 256
#define PST 25               // padded row stride in smem

__global__ __launch_bounds__(ETHREADS)
void moe_epilogue_kernel(const float* __restrict__ gate_b,
                         const float* __restrict__ ebias,
                         const float* __restrict__ expert_b,
                         float* __restrict__ out,
                         float* __restrict__ idx_out)
{
    __shared__ float Ppart[SPLITK * ETOK][PST];   // 12.8 KB
    __shared__ float Pfin[ETOK][PST];             // 3.2 KB
    __shared__ float wtok[ETOK];

    const int tid   = threadIdx.x;
    const int tok0  = blockIdx.x * ETOK;

    // ---- Phase A: thread = (split = tid>>5 [0..7 -> but SPLITK=4 uses 2 passes? no])
    // 256 threads = 32 tokens x 8 slots; with SPLITK=4, slots 0..3 load, 4..7 idle-load pattern
    // Simpler: slot = tid>>5 in [0,8); each slot s<SPLITK loads its split, else zeros.
    {
        const int token = tid & 31;
        const int slot  = tid >> 5;            // 0..7
        float* dst = &Ppart[(slot & (SPLITK - 1)) * ETOK + token][0];
        if (slot < SPLITK) {
            const float* src = g_scratch + (size_t)(slot * NROW) * BTOK + tok0 + token;
            #pragma unroll
            for (int r = 0; r < NROW; r++)
                dst[r] = src[(size_t)r * BTOK];    // coalesced across lanes
        }
    }
    __syncthreads();

    // ---- Phase B: 768 cells (32 tok x 24 rows), 3 per thread, sum 4 splits ----
    #pragma unroll
    for (int cbase = 0; cbase < 3; cbase++) {
        int cell  = tid * 3 + cbase;           // 0..767
        int token = cell / NROW;
        int r     = cell - token * NROW;
        float s = 0.f;
        #pragma unroll
        for (int sp = 0; sp < SPLITK; sp++)
            s += Ppart[sp * ETOK + token][r];
        Pfin[token][r] = s;
    }
    __syncthreads();

    // ---- Phase C: gating (threads 0..31) ----
    if (tid < ETOK) {
        const float* Pm = &Pfin[tid][0];
        float l[NE];
        #pragma unroll
        for (int e = 0; e < NE; e++)
            l[e] = Pm[e] + gate_b[e] + ebias[e];

        int e0 = 0; float b0 = l[0];
        #pragma unroll
        for (int e = 1; e < NE; e++)
            if (l[e] > b0) { b0 = l[e]; e0 = e; }
        int e1 = -1; float b1 = -INFINITY;
        #pragma unroll
        for (int e = 0; e < NE; e++) {
            if (e == e0) continue;
            if (l[e] > b1) { b1 = l[e]; e1 = e; }
        }

        float p0 = 1.f / (1.f + expf(-b0));
        float p1 = 1.f / (1.f + expf(-b1));
        float inv = 1.f / (p0 + p1);

        float v0 = Pm[NE + e0 * 2 + 0] + expert_b[(size_t)e0 * DOUT + 0];
        float v1 = Pm[NE + e1 * 2 + 1] + expert_b[(size_t)e1 * DOUT + 1];
        wtok[tid] = (v0 * p0 + v1 * p1) * inv;

        if (idx_out) {
            idx_out[(size_t)(tok0 + tid) * 2 + 0] = (float)e0;
            idx_out[(size_t)(tok0 + tid) * 2 + 1] = (float)e1;
        }
    }
    __syncthreads();

    // ---- Phase D: broadcast write, 256 threads x float4 = 1024 floats/token ----
    const int fo = tid << 2;
    #pragma unroll 4
    for (int m = 0; m < ETOK; m++) {
        float v = wtok[m];
        float4 v4 = make_float4(v, v, v, v);
        *(float4*)(out + (size_t)(tok0 + m) * DOUT + fo) = v4;
    }
}

extern "C" void kernel_launch(void* const* d_in, const int* in_sizes, int n_in,
                              void* d_out, int out_size)
{
    const float* x        = (const float*)d_in[0];
    const float* gate_w   = (const float*)d_in[1];
    const float* gate_b   = (const float*)d_in[2];
    const float* ebias    = (const float*)d_in[3];
    const float* expert_w = (const float*)d_in[4];
    const float* expert_b = (const float*)d_in[5];
    float* out = (float*)d_out;

    float* idx_out = nullptr;
    long long base = (long long)BTOK * DOUT;
    if ((long long)out_size >= base + (long long)BTOK * 2)
        idx_out = out + base;

    moe_gemm_kernel<<<(BTOK / TMB) * SPLITK, GTHREADS>>>(x, gate_w, expert_w);
    moe_epilogue_kernel<<<BTOK / ETOK, ETHREADS>>>(gate_b, ebias, expert_b,
                                                   out, idx_out);
}